// round 4
// baseline (speedup 1.0000x reference)
#include <cuda_runtime.h>
#include <math.h>

// Problem constants
#define NB 64
#define NF 36
#define NQ 100
#define NQP 101                         // auction smem stride (conflict-free)
#define NT 20
#define NC 92
#define NCP 93                          // logits smem stride
#define NQUERY (NB * NF * NQ)          // 230400
#define NINST  (NB * NF)               // 2304
#define COST_ELEMS (NQUERY * NT)       // 4608000
#define IDX_ELEMS  (NINST * NT)        // 46080

// ---------------------------------------------------------------------------
// Fused kernel: block = one (b,f) instance.
//   Phase A (128 thr): stage logits -> compute 100x20 cost -> ben in smem
//                      -> coalesced cost store to gmem.
//   Phase B (warp 0, warps 1-3 exit): Jacobi auction on smem benefit,
//                      then argsort + index outputs.
// ---------------------------------------------------------------------------
__global__ __launch_bounds__(128) void fused_kernel(
        const float* __restrict__ logits,
        const float* __restrict__ pboxes,
        const int*   __restrict__ tlabels,
        const float* __restrict__ tboxes,
        float* __restrict__ cost,
        float* __restrict__ out_pred,
        float* __restrict__ out_tgt)
{
    const int inst = blockIdx.x;          // b*36 + f
    const int b = inst / NF;
    const int f = inst - b * NF;
    const int tid = threadIdx.x;
    const int lane = tid & 31;
    const int warp = tid >> 5;

    __shared__ float sh[NQ * NCP];        // 37.2 KB; later reused: ben = sh[0..2019]
    __shared__ float4 stbc[NT];           // target cxcywh
    __shared__ float4 stbx[NT];           // target xyxy
    __shared__ float  sarea[NT];
    __shared__ int    slab[NT];
    __shared__ float  wmx[4], wmn[4];
    // auction state
    __shared__ float price[NQ];
    __shared__ int   owner[NQ];
    __shared__ int   obj_of[NT];
    __shared__ float sbid[NT];
    __shared__ int   sobj[NT];
    __shared__ int   blist[NT];

    // --- stage logits: 100*92 floats = 2300 float4 (23 per row) ---
    const float4* lg4 = (const float4*)(logits + ((size_t)b * (NF * NQ) + f * NQ) * NC);
    #pragma unroll 4
    for (int i = tid; i < NQ * (NC / 4); i += 128) {
        const float4 v = lg4[i];
        const int q  = i / 23;
        const int c4 = (i - q * 23) * 4;
        float* dst = &sh[q * NCP + c4];
        dst[0] = v.x; dst[1] = v.y; dst[2] = v.z; dst[3] = v.w;
    }

    // --- stage targets ---
    if (tid < NT) {
        const size_t tb_ = (size_t)(f * NB + b) * NT + tid;
        const float4 tb = ((const float4*)tboxes)[tb_];
        stbc[tid] = tb;
        const float x0 = tb.x - 0.5f * tb.z, y0 = tb.y - 0.5f * tb.w;
        const float x1 = tb.x + 0.5f * tb.z, y1 = tb.y + 0.5f * tb.w;
        stbx[tid]  = make_float4(x0, y0, x1, y1);
        sarea[tid] = (x1 - x0) * (y1 - y0);
        slab[tid]  = tlabels[tb_];
    }
    __syncthreads();

    // --- per-query cost into registers ---
    float res[NT];
    float mx = -INFINITY, mn = INFINITY;
    const int q = tid;
    if (q < NQ) {
        const float* row = &sh[q * NCP];

        float s = 0.0f;
        #pragma unroll 4
        for (int c = 0; c < NC; ++c) s += __expf(row[c]);
        const float rs = __fdividef(1.0f, s);

        const float4 pb = *(const float4*)(pboxes + ((size_t)b * (NF * NQ) + f * NQ + q) * 4);
        const float px0 = pb.x - 0.5f * pb.z;
        const float py0 = pb.y - 0.5f * pb.w;
        const float px1 = pb.x + 0.5f * pb.z;
        const float py1 = pb.y + 0.5f * pb.w;
        const float area1 = (px1 - px0) * (py1 - py0);

        #pragma unroll
        for (int t = 0; t < NT; ++t) {
            const float prob = __expf(row[slab[t]]) * rs;

            const float4 tc = stbc[t];
            const float l1 = fabsf(pb.x - tc.x) + fabsf(pb.y - tc.y)
                           + fabsf(pb.z - tc.z) + fabsf(pb.w - tc.w);

            const float4 tx = stbx[t];
            const float ltx = fmaxf(px0, tx.x), lty = fmaxf(py0, tx.y);
            const float rbx = fminf(px1, tx.z), rby = fminf(py1, tx.w);
            const float iw = fmaxf(rbx - ltx, 0.0f), ih = fmaxf(rby - lty, 0.0f);
            const float inter = iw * ih;
            const float uni = area1 + sarea[t] - inter;
            const float iou = __fdividef(inter, uni);

            const float elx = fminf(px0, tx.x), ely = fminf(py0, tx.y);
            const float erx = fmaxf(px1, tx.z), ery = fmaxf(py1, tx.w);
            const float ew = fmaxf(erx - elx, 0.0f), eh = fmaxf(ery - ely, 0.0f);
            const float areae = ew * eh;
            const float giou = iou - __fdividef(areae - uni, areae);

            const float cv = -prob + 5.0f * l1 - 2.0f * giou;
            res[t] = cv;
            const float bv = -cv;               // benefit
            mx = fmaxf(mx, bv);
            mn = fminf(mn, bv);
        }
    }
    // warp reduce mx/mn (inactive threads hold -inf/+inf)
    #pragma unroll
    for (int o = 16; o > 0; o >>= 1) {
        mx = fmaxf(mx, __shfl_xor_sync(0xffffffffu, mx, o));
        mn = fminf(mn, __shfl_xor_sync(0xffffffffu, mn, o));
    }
    if (lane == 0) { wmx[warp] = mx; wmn[warp] = mn; }
    __syncthreads();   // logits in sh now dead; res/mx safely captured

    // --- build benefit matrix in reused smem (ben = sh[0..NT*NQP)) ---
    float* ben = sh;
    if (q < NQ) {
        #pragma unroll
        for (int t = 0; t < NT; ++t) ben[t * NQP + q] = -res[t];
    }
    // auction state init by whole block
    for (int i = tid; i < NQ; i += 128) { price[i] = 0.0f; owner[i] = -1; }
    if (tid < NT) obj_of[tid] = -1;
    __syncthreads();

    // --- coalesced cost store (read back from ben) ---
    float* cbase = cost + (size_t)inst * (NQ * NT);
    #pragma unroll 4
    for (int i = tid; i < NQ * NT; i += 128) {
        const int q2 = i / NT, t2 = i - q2 * NT;
        cbase[i] = -ben[t2 * NQP + q2];
    }

    // warps 1..3 are done
    if (warp != 0) return;

    // =======================================================================
    // Phase B: auction on warp 0 (t = lane; bidders are t<20)
    // =======================================================================
    const int t = lane;
    const float gmx = fmaxf(fmaxf(wmx[0], wmx[1]), fmaxf(wmx[2], wmx[3]));
    const float gmn = fminf(fminf(wmn[0], wmn[1]), fminf(wmn[2], wmn[3]));
    const float eps = (gmx - gmn + 1e-06f) / 1000.0f;
    __syncwarp();

    for (int it = 0; it < 20000; ++it) {
        const bool un = (t < NT) && (obj_of[t] < 0);
        const unsigned mask = __ballot_sync(0xffffffffu, un);
        if (!mask) break;
        const int u = __popc(mask);

        if (un) blist[__popc(mask & ((1u << t) - 1u))] = t;
        __syncwarp();

        const int gp = 32 / u;
        const int gsize = 1 << (31 - __clz(gp));
        const int grp = t / gsize;
        const int lig = t - grp * gsize;
        const bool live = (grp < u);
        const int t2 = blist[live ? grp : 0];

        float b1 = -INFINITY, b2 = -INFINITY;
        int i1 = 0;
        const float* br = &ben[t2 * NQP];
        for (int qq = lig; qq < NQ; qq += gsize) {
            const float v = br[qq] - price[qq];
            if (v > b1) { b2 = b1; b1 = v; i1 = qq; }
            else if (v > b2) { b2 = v; }
        }
        for (int o = gsize >> 1; o > 0; o >>= 1) {
            const float ob1 = __shfl_xor_sync(0xffffffffu, b1, o);
            const int   oi1 = __shfl_xor_sync(0xffffffffu, i1, o);
            const float ob2 = __shfl_xor_sync(0xffffffffu, b2, o);
            const bool aw = (b1 > ob1) || (b1 == ob1 && i1 < oi1);
            const float lose = aw ? ob1 : b1;
            b2 = fmaxf(lose, fmaxf(b2, ob2));
            b1 = aw ? b1 : ob1;
            i1 = aw ? i1 : oi1;
        }
        if (live && lig == 0) {
            sbid[t2] = price[i1] + (b1 - b2) + eps;
            sobj[t2] = i1;
        }
        __syncwarp();

        bool winf = false;
        int myq = -1;
        if (un) {
            myq = sobj[t];
            const float mybid = sbid[t];
            winf = true;
            for (unsigned mm = mask & ~(1u << t); mm; mm &= mm - 1u) {
                const int t3 = __ffs(mm) - 1;
                if (sobj[t3] == myq) {
                    const float ob = sbid[t3];
                    if (ob > mybid || (ob == mybid && t3 < t)) winf = false;
                }
            }
        }
        __syncwarp();

        int old = -1;
        if (winf) old = owner[myq];
        __syncwarp();
        if (winf && old >= 0) obj_of[old] = -1;   // evictions first
        __syncwarp();
        if (winf) {
            obj_of[t] = myq;
            price[myq] = sbid[t];
            owner[myq] = t;
        }
        __syncwarp();
    }

    // argsort(obj_of) ascending, stable
    if (t < NT) {
        const int v = obj_of[t];
        int rank = 0;
        #pragma unroll
        for (int t3 = 0; t3 < NT; ++t3) {
            const int v2 = obj_of[t3];
            rank += (v2 < v) || (v2 == v && t3 < t);
        }
        out_pred[(size_t)inst * NT + rank] = (float)v;
        out_tgt [(size_t)inst * NT + rank] = (float)t;
    }
}

// ---------------------------------------------------------------------------
extern "C" void kernel_launch(void* const* d_in, const int* in_sizes, int n_in,
                              void* d_out, int out_size)
{
    const float* logits  = (const float*)d_in[0];  // (64, 3600, 92)
    const float* pboxes  = (const float*)d_in[1];  // (64, 3600, 4)
    const int*   tlabels = (const int*)  d_in[2];  // (36, 64, 20)
    const float* tboxes  = (const float*)d_in[3];  // (36, 64, 20, 4)

    float* out  = (float*)d_out;
    float* cost = out;
    float* pidx = out + COST_ELEMS;
    float* tidx = out + COST_ELEMS + IDX_ELEMS;

    fused_kernel<<<NINST, 128>>>(logits, pboxes, tlabels, tboxes,
                                 cost, pidx, tidx);
}